// round 14
// baseline (speedup 1.0000x reference)
#include <cuda_runtime.h>
#include <cuda_fp16.h>
#include <cstdint>

#define F0n   39
#define Dn    16
#define HOUT  256
#define K1    1521
#define K2    4992
#define NL1U  80          // L1 units: 40 f (39 valid + 1 zero) x 2 halves
#define NUNIT 236         // + 156 L2 units
#define NG1   20          // L1 groups of 4 units (2 f)
#define NG2   39          // L2 groups of 4 units (4 chunks)

#define SLOT_SZ   8192
#define XS_OFF    65536                 // float xs[64][40]    10240 B
#define H1S_OFF   75776                 // float h1s[64][132]  33792 B
#define SMEM_TOTAL 109568               // per CTA; 2 CTAs/SM

typedef unsigned long long u64;

// Unified weight units: [unit][64 rows][128B split-row], 32 k each, XOR-swizzled.
// units 0..79: L1 (f = u>>1, k block = (u&1)*32); 80..235: L2 (ci = u-80).
__device__ __half g_Wc[NUNIT * 4096];

__device__ __forceinline__ uint32_t smem_u32(const void* p) {
    uint32_t a;
    asm("{ .reg .u64 t; cvta.to.shared.u64 t, %1; cvt.u32.u64 %0, t; }" : "=r"(a) : "l"(p));
    return a;
}
__device__ __forceinline__ u64 dup2(float v) {
    u64 r; asm("mov.b64 %0, {%1, %1};" : "=l"(r) : "f"(v)); return r;
}
// A-fragment word: fp16x2( s2 * p2 ), low lane = first element
__device__ __forceinline__ uint32_t amul(u64 s2, u64 p2) {
    u64 p; asm("mul.rn.f32x2 %0, %1, %2;" : "=l"(p) : "l"(s2), "l"(p2));
    uint32_t lo, hi; asm("mov.b64 {%0, %1}, %2;" : "=r"(lo), "=r"(hi) : "l"(p));
    uint32_t r; asm("cvt.rn.f16x2.f32 %0, %1, %2;" : "=r"(r) : "r"(hi), "r"(lo));
    return r;
}

#define CP16(dst, src) \
    asm volatile("cp.async.cg.shared.global [%0], [%1], 16;" :: "r"(dst), "l"(src))
#define CP_COMMIT() asm volatile("cp.async.commit_group;" ::: "memory")
#define CP_WAIT0()  asm volatile("cp.async.wait_group 0;" ::: "memory")
#define CP_WAIT1()  asm volatile("cp.async.wait_group 1;" ::: "memory")

#define LDSM_X4(r0, r1, r2, r3, addr) \
    asm volatile("ldmatrix.sync.aligned.m8n8.x4.shared.b16 {%0,%1,%2,%3}, [%4];" \
                 : "=r"(r0), "=r"(r1), "=r"(r2), "=r"(r3) : "r"(addr))

#define MMA16816H(d, a, b0_, b1_) \
    asm volatile("mma.sync.aligned.m16n8k16.row.col.f32.f16.f16.f32 " \
                 "{%0,%1,%2,%3}, {%4,%5,%6,%7}, {%8,%9}, {%0,%1,%2,%3};" \
                 : "+f"((d)[0]), "+f"((d)[1]), "+f"((d)[2]), "+f"((d)[3]) \
                 : "r"((a)[0]), "r"((a)[1]), "r"((a)[2]), "r"((a)[3]), \
                   "r"(b0_), "r"(b1_))

struct BC { uint32_t row[2]; uint32_t hf[2]; uint32_t xo[2]; uint32_t sel; };

// ---------------- weight prep (unified) ----------------
__global__ void prep_w(const float* __restrict__ W0, const float* __restrict__ W1) {
    int idx = blockIdx.x * 256 + threadIdx.x;
    if (idx >= NUNIT * 4096) return;
    int u  = idx >> 12;
    int h  = (idx >> 5) & 127;
    int kl = idx & 31;
    float w = 0.f;
    if (u < NL1U) {
        int f = u >> 1;
        int ks = (u & 1) * 32 + kl;
        if (f < F0n && ks < F0n) w = W0[h * K1 + f * F0n + ks];
    } else {
        int ci = u - NL1U;
        int qq = ci / F0n;
        int f  = ci - qq * F0n;
        w = W1[h * K2 + f * 128 + qq * 32 + kl];
    }
    uint32_t byte = (uint32_t)(h & 63) * 128 +
        ((((uint32_t)(h >> 6) * 64) + (uint32_t)kl * 2) ^ ((uint32_t)(h & 7) << 4));
    g_Wc[u * 4096 + (byte >> 1)] = __float2half_rn(w);
}

// ---------------- staging: one 8KB unit = 2 CP16/thread (256 thr) ----------------
__device__ __forceinline__ void stage_unit(uint32_t sb, int u, int tid) {
    const uint32_t dst = sb + (u & 7) * SLOT_SZ;
    const __half* src = g_Wc + u * 4096;
    CP16(dst + tid * 16, src + tid * 8);
    CP16(dst + (tid + 256) * 16, src + (tid + 256) * 8);
}

// ---------------- B-fragment LDSM ----------------
__device__ __forceinline__ void ldsm_b(uint32_t B[8], uint32_t base, uint32_t kslOff,
                                       const BC& bc) {
    #pragma unroll
    for (int pr = 0; pr < 2; pr++) {
        uint32_t bd = base + bc.row[pr] + ((bc.hf[pr] + kslOff + bc.sel) ^ bc.xo[pr]);
        LDSM_X4(B[pr * 4 + 0], B[pr * 4 + 1], B[pr * 4 + 2], B[pr * 4 + 3], bd);
    }
}

// ---------------- L1 group: 2 f-chunks, 6 ks-blocks, B ping-pong ----------------
__device__ __forceinline__ void l1_group(
    uint32_t sb, int g, const float* xs,
    const u64 xa2a[2][3][2], const u64 xa2b[2][2][2],
    float acc[2][4][4], int m0, int r, const BC& bc)
{
    const int u0 = 4 * g;
    const int f0 = 2 * g;
    const int so[6] = {0, 0, 1, 2, 2, 3};
    const int ko[6] = {0, 32, 0, 0, 32, 0};
    const int qj[6] = {0, 1, 2, 0, 1, 2};
    uint32_t B[2][8];
    u64 xr2[2][2];
    ldsm_b(B[0], sb + ((u0 + 0) & 7) * SLOT_SZ, 0, bc);
    #pragma unroll
    for (int st = 0; st < 6; st++) {
        if (st == 0 || st == 3) {
            const int f = f0 + (st == 3 ? 1 : 0);
            #pragma unroll
            for (int mt = 0; mt < 2; mt++) {
                xr2[mt][0] = dup2(xs[(m0 + mt * 16 + r) * 40 + f]);
                xr2[mt][1] = dup2(xs[(m0 + mt * 16 + r + 8) * 40 + f]);
            }
        }
        if (st < 5)
            ldsm_b(B[(st + 1) & 1], sb + ((u0 + so[st + 1]) & 7) * SLOT_SZ,
                   (uint32_t)ko[st + 1], bc);
        const int q = qj[st];
        #pragma unroll
        for (int mt = 0; mt < 2; mt++) {
            uint32_t A[4];
            A[0] = amul(xr2[mt][0], xa2a[mt][q][0]);
            A[1] = amul(xr2[mt][1], xa2a[mt][q][1]);
            if (q < 2) {
                A[2] = amul(xr2[mt][0], xa2b[mt][q][0]);
                A[3] = amul(xr2[mt][1], xa2b[mt][q][1]);
            } else { A[2] = 0u; A[3] = 0u; }
            #pragma unroll
            for (int ht = 0; ht < 4; ht++)
                MMA16816H(acc[mt][ht], A, B[st & 1][ht * 2], B[st & 1][ht * 2 + 1]);
        }
    }
}

// ---------------- L2 group: 4 chunks, 8 ks-blocks, B ping-pong ----------------
__device__ __forceinline__ void l2_group(
    uint32_t sb, int g, const float* xs, const float* h1s,
    u64 hv2[2][2][4], int& f_cur, int& qq_cur,
    float acc[2][4][4], int m0, int r, int c2, const BC& bc)
{
    const int u0 = NL1U + 4 * g;
    uint32_t B[2][8];
    u64 xr2[2][2];
    ldsm_b(B[0], sb + (u0 & 7) * SLOT_SZ, 0, bc);
    #pragma unroll
    for (int st = 0; st < 8; st++) {
        if ((st & 1) == 0) {
            if (f_cur == F0n) { f_cur = 0; qq_cur++; }
            if (f_cur == 0) {
                #pragma unroll
                for (int mt = 0; mt < 2; mt++) {
                    const int n = m0 + mt * 16 + r;
                    #pragma unroll
                    for (int ks = 0; ks < 2; ks++) {
                        const int q0 = qq_cur * 32 + ks * 16 + c2;
                        hv2[mt][ks][0] = *(const u64*)&h1s[n * 132 + q0];
                        hv2[mt][ks][1] = *(const u64*)&h1s[(n + 8) * 132 + q0];
                        hv2[mt][ks][2] = *(const u64*)&h1s[n * 132 + q0 + 8];
                        hv2[mt][ks][3] = *(const u64*)&h1s[(n + 8) * 132 + q0 + 8];
                    }
                }
            }
            #pragma unroll
            for (int mt = 0; mt < 2; mt++) {
                xr2[mt][0] = dup2(xs[(m0 + mt * 16 + r) * 40 + f_cur]);
                xr2[mt][1] = dup2(xs[(m0 + mt * 16 + r + 8) * 40 + f_cur]);
            }
        }
        if (st < 7) {
            const int nst = st + 1;
            ldsm_b(B[nst & 1], sb + ((u0 + (nst >> 1)) & 7) * SLOT_SZ,
                   (uint32_t)((nst & 1) * 32), bc);
        }
        const int ks = st & 1;
        #pragma unroll
        for (int mt = 0; mt < 2; mt++) {
            uint32_t A[4];
            A[0] = amul(xr2[mt][0], hv2[mt][ks][0]);
            A[1] = amul(xr2[mt][1], hv2[mt][ks][1]);
            A[2] = amul(xr2[mt][0], hv2[mt][ks][2]);
            A[3] = amul(xr2[mt][1], hv2[mt][ks][3]);
            #pragma unroll
            for (int ht = 0; ht < 4; ht++)
                MMA16816H(acc[mt][ht], A, B[ks][ht * 2], B[ks][ht * 2 + 1]);
        }
        if (st & 1) f_cur++;
    }
}

// ---------------- main kernel: 256 threads, 2 CTAs/SM ----------------
__global__ __launch_bounds__(256, 2)
void cin_main(const float* __restrict__ x, float* __restrict__ out) {
    extern __shared__ __align__(1024) char smem[];
    const uint32_t sb = smem_u32(smem);
    float* xs  = (float*)(smem + XS_OFF);
    float* h1s = (float*)(smem + H1S_OFF);

    const int tid  = threadIdx.x;
    const int lane = tid & 31;
    const int warp = tid >> 5;            // 0..7
    const int m0 = (warp & 1) * 32;       // 2 m-groups (n = 64)
    const int h0 = (warp >> 1) * 32;      // 4 h-groups
    const int b0 = blockIdx.x * 4;        // 4 batches (64 columns) per CTA
    const int r  = lane >> 2;
    const int c2 = (lane & 3) * 2;

    BC bc;
    #pragma unroll
    for (int pr = 0; pr < 2; pr++) {
        int hB = h0 + pr * 16 + (lane >> 4) * 8 + (lane & 7);
        bc.xo[pr]  = (uint32_t)(hB & 7) << 4;
        bc.row[pr] = (uint32_t)(hB & 63) * 128;
        bc.hf[pr]  = (uint32_t)(hB >> 6) * 64;
    }
    bc.sel = (uint32_t)((lane >> 3) & 1) * 16;

    // prologue: stage units 0-3, 4-7
    stage_unit(sb, 0, tid); stage_unit(sb, 1, tid);
    stage_unit(sb, 2, tid); stage_unit(sb, 3, tid); CP_COMMIT();
    stage_unit(sb, 4, tid); stage_unit(sb, 5, tid);
    stage_unit(sb, 6, tid); stage_unit(sb, 7, tid); CP_COMMIT();

    // xs[n][f], n = (b_local<<4)|d ; col 39 zeroed
    for (int i = tid; i < F0n * 64; i += 256) {
        int f = i >> 6, cc = i & 63;
        int b = b0 + (cc >> 4), d = cc & 15;
        xs[cc * 40 + f] = x[(b * F0n + f) * Dn + d];
    }
    for (int i = tid; i < 64; i += 256) xs[i * 40 + 39] = 0.f;
    CP_WAIT1();
    __syncthreads();

    float acc[2][4][4];
    #pragma unroll
    for (int mt = 0; mt < 2; mt++)
        #pragma unroll
        for (int ht = 0; ht < 4; ht++)
            #pragma unroll
            for (int j = 0; j < 4; j++) acc[mt][ht][j] = 0.f;

    // resident x pairs (packed f32x2)
    u64 xa2a[2][3][2], xa2b[2][2][2];
    #pragma unroll
    for (int mt = 0; mt < 2; mt++) {
        const int n = m0 + mt * 16 + r;
        #pragma unroll
        for (int ks = 0; ks < 3; ks++) {
            const int q0 = ks * 16 + c2;                 // <= 38; q0+1 <= 39 (col 39 = 0)
            xa2a[mt][ks][0] = *(const u64*)&xs[n * 40 + q0];
            xa2a[mt][ks][1] = *(const u64*)&xs[(n + 8) * 40 + q0];
        }
        #pragma unroll
        for (int ks = 0; ks < 2; ks++) {
            const int q0 = ks * 16 + c2 + 8;             // <= 31, always valid
            xa2b[mt][ks][0] = *(const u64*)&xs[n * 40 + q0];
            xa2b[mt][ks][1] = *(const u64*)&xs[(n + 8) * 40 + q0];
        }
    }

    // ================= Layer 1 =================
    #pragma unroll 1
    for (int g = 0; g < NG1; g++) {
        l1_group(sb, g, xs, xa2a, xa2b, acc, m0, r, bc);
        CP_WAIT0();
        __syncthreads();
        const int t = 4 * g + 8;                          // max 87 < NUNIT
        stage_unit(sb, t, tid);     stage_unit(sb, t + 1, tid);
        stage_unit(sb, t + 2, tid); stage_unit(sb, t + 3, tid);
        CP_COMMIT();
    }

    // L1 epilogue: acc -> h1s fp32 (feeds L2 resident + out1)
    #pragma unroll
    for (int mt = 0; mt < 2; mt++)
        #pragma unroll
        for (int ht = 0; ht < 4; ht++) {
            const int n = m0 + mt * 16 + r;
            const int h = h0 + ht * 8 + c2;
            *(float2*)&h1s[n * 132 + h] = make_float2(acc[mt][ht][0], acc[mt][ht][1]);
            *(float2*)&h1s[(n + 8) * 132 + h] = make_float2(acc[mt][ht][2], acc[mt][ht][3]);
        }
    __syncthreads();
    #pragma unroll
    for (int rr = 0; rr < 2; rr++) {
        const int idx = rr * 256 + tid;                  // 512 outputs (4 bl x 128 h)
        const int bl = idx >> 7, h = idx & 127;
        float s = 0.f;
        #pragma unroll
        for (int d = 0; d < 16; d++) s += h1s[(bl * 16 + d) * 132 + h];
        out[(b0 + bl) * HOUT + h] = s;
    }
    __syncthreads();

    // ================= Layer 2 =================
    #pragma unroll
    for (int mt = 0; mt < 2; mt++)
        #pragma unroll
        for (int ht = 0; ht < 4; ht++)
            #pragma unroll
            for (int j = 0; j < 4; j++) acc[mt][ht][j] = 0.f;

    {
        u64 hv2[2][2][4];
        int f_cur = 0, qq_cur = 0;
        #pragma unroll 1
        for (int g = 0; g < NG2; g++) {
            l2_group(sb, g, xs, h1s, hv2, f_cur, qq_cur, acc, m0, r, c2, bc);
            CP_WAIT0();
            __syncthreads();
            const int t = NL1U + 4 * g + 8;
            #pragma unroll
            for (int i = 0; i < 4; i++)
                if (t + i < NUNIT) stage_unit(sb, t + i, tid);
            CP_COMMIT();
        }
    }

    // L2 epilogue
    #pragma unroll
    for (int mt = 0; mt < 2; mt++)
        #pragma unroll
        for (int ht = 0; ht < 4; ht++) {
            const int n = m0 + mt * 16 + r;
            const int h = h0 + ht * 8 + c2;
            *(float2*)&h1s[n * 132 + h] = make_float2(acc[mt][ht][0], acc[mt][ht][1]);
            *(float2*)&h1s[(n + 8) * 132 + h] = make_float2(acc[mt][ht][2], acc[mt][ht][3]);
        }
    __syncthreads();
    #pragma unroll
    for (int rr = 0; rr < 2; rr++) {
        const int idx = rr * 256 + tid;
        const int bl = idx >> 7, h = idx & 127;
        float s = 0.f;
        #pragma unroll
        for (int d = 0; d < 16; d++) s += h1s[(bl * 16 + d) * 132 + h];
        out[(b0 + bl) * HOUT + 128 + h] = s;
    }
}

extern "C" void kernel_launch(void* const* d_in, const int* in_sizes, int n_in,
                              void* d_out, int out_size) {
    const float* xin = (const float*)d_in[0];
    const float* W0  = (const float*)d_in[1];
    const float* W1  = (const float*)d_in[2];
    float* out = (float*)d_out;

    prep_w<<<(NUNIT * 4096 + 255) / 256, 256>>>(W0, W1);

    cudaFuncSetAttribute(cin_main, cudaFuncAttributeMaxDynamicSharedMemorySize, SMEM_TOTAL);
    cin_main<<<512, 256, SMEM_TOTAL>>>(xin, out);
}

// round 15
// speedup vs baseline: 1.0036x; 1.0036x over previous
#include <cuda_runtime.h>
#include <cuda_fp16.h>
#include <cstdint>

#define F0n   39
#define Dn    16
#define HOUT  256
#define K1    1521
#define K2    4992
#define NL1U  80          // L1 units: 40 f (39 valid + 1 zero) x 2 halves
#define NUNIT 236         // + 156 L2 units
#define NG1   20          // L1 groups of 4 units (2 f)
#define NG2   39          // L2 groups of 4 units (4 chunks)

#define SLOT_SZ   8192
#define XS_OFF    65536                 // float xs[64][40]    10240 B
#define H1S_OFF   75776                 // float h1s[64][132]  33792 B
#define SMEM_TOTAL 109568               // per CTA; 2 CTAs/SM

typedef unsigned long long u64;

// Unified weight units: [unit][64 rows][128B split-row], 32 k each, XOR-swizzled.
// units 0..79: L1 (f = u>>1, k block = (u&1)*32); 80..235: L2 (ci = u-80).
__device__ __half g_Wc[NUNIT * 4096];

__device__ __forceinline__ uint32_t smem_u32(const void* p) {
    uint32_t a;
    asm("{ .reg .u64 t; cvta.to.shared.u64 t, %1; cvt.u32.u64 %0, t; }" : "=r"(a) : "l"(p));
    return a;
}
__device__ __forceinline__ u64 dup2(float v) {
    u64 r; asm("mov.b64 %0, {%1, %1};" : "=l"(r) : "f"(v)); return r;
}
// A-fragment word: fp16x2( s2 * p2 ), low lane = first element
__device__ __forceinline__ uint32_t amul(u64 s2, u64 p2) {
    u64 p; asm("mul.rn.f32x2 %0, %1, %2;" : "=l"(p) : "l"(s2), "l"(p2));
    uint32_t lo, hi; asm("mov.b64 {%0, %1}, %2;" : "=r"(lo), "=r"(hi) : "l"(p));
    uint32_t r; asm("cvt.rn.f16x2.f32 %0, %1, %2;" : "=r"(r) : "r"(hi), "r"(lo));
    return r;
}

#define CP16(dst, src) \
    asm volatile("cp.async.cg.shared.global [%0], [%1], 16;" :: "r"(dst), "l"(src))
#define CP_COMMIT() asm volatile("cp.async.commit_group;" ::: "memory")
#define CP_WAIT0()  asm volatile("cp.async.wait_group 0;" ::: "memory")
#define CP_WAIT1()  asm volatile("cp.async.wait_group 1;" ::: "memory")

#define LDSM_X4(r0, r1, r2, r3, addr) \
    asm volatile("ldmatrix.sync.aligned.m8n8.x4.shared.b16 {%0,%1,%2,%3}, [%4];" \
                 : "=r"(r0), "=r"(r1), "=r"(r2), "=r"(r3) : "r"(addr))

#define MMA16816H(d, a, b0_, b1_) \
    asm volatile("mma.sync.aligned.m16n8k16.row.col.f32.f16.f16.f32 " \
                 "{%0,%1,%2,%3}, {%4,%5,%6,%7}, {%8,%9}, {%0,%1,%2,%3};" \
                 : "+f"((d)[0]), "+f"((d)[1]), "+f"((d)[2]), "+f"((d)[3]) \
                 : "r"((a)[0]), "r"((a)[1]), "r"((a)[2]), "r"((a)[3]), \
                   "r"(b0_), "r"(b1_))

struct BC { uint32_t row[2]; uint32_t hf[2]; uint32_t xo[2]; uint32_t sel; };

// ---------------- weight prep (unified) ----------------
__global__ void prep_w(const float* __restrict__ W0, const float* __restrict__ W1) {
    int idx = blockIdx.x * 256 + threadIdx.x;
    if (idx >= NUNIT * 4096) return;
    int u  = idx >> 12;
    int h  = (idx >> 5) & 127;
    int kl = idx & 31;
    float w = 0.f;
    if (u < NL1U) {
        int f = u >> 1;
        int ks = (u & 1) * 32 + kl;
        if (f < F0n && ks < F0n) w = W0[h * K1 + f * F0n + ks];
    } else {
        int ci = u - NL1U;
        int qq = ci / F0n;
        int f  = ci - qq * F0n;
        w = W1[h * K2 + f * 128 + qq * 32 + kl];
    }
    uint32_t byte = (uint32_t)(h & 63) * 128 +
        ((((uint32_t)(h >> 6) * 64) + (uint32_t)kl * 2) ^ ((uint32_t)(h & 7) << 4));
    g_Wc[u * 4096 + (byte >> 1)] = __float2half_rn(w);
}

// ---------------- staging: one 8KB unit = 2 CP16/thread (256 thr) ----------------
__device__ __forceinline__ void stage_unit(uint32_t sb, int u, int tid) {
    const uint32_t dst = sb + (u & 7) * SLOT_SZ;
    const __half* src = g_Wc + u * 4096;
    CP16(dst + tid * 16, src + tid * 8);
    CP16(dst + (tid + 256) * 16, src + (tid + 256) * 8);
}

// ---------------- B-fragment LDSM ----------------
__device__ __forceinline__ void ldsm_b(uint32_t B[8], uint32_t base, uint32_t kslOff,
                                       const BC& bc) {
    #pragma unroll
    for (int pr = 0; pr < 2; pr++) {
        uint32_t bd = base + bc.row[pr] + ((bc.hf[pr] + kslOff + bc.sel) ^ bc.xo[pr]);
        LDSM_X4(B[pr * 4 + 0], B[pr * 4 + 1], B[pr * 4 + 2], B[pr * 4 + 3], bd);
    }
}

// ---------------- L1 group: 2 f-chunks, 6 ks-blocks, B ping-pong ----------------
__device__ __forceinline__ void l1_group(
    uint32_t sb, int g, const float* xs,
    const u64 xa2a[2][3][2], const u64 xa2b[2][2][2],
    float acc[2][4][4], int m0, int r, const BC& bc)
{
    const int u0 = 4 * g;
    const int f0 = 2 * g;
    const int so[6] = {0, 0, 1, 2, 2, 3};
    const int ko[6] = {0, 32, 0, 0, 32, 0};
    const int qj[6] = {0, 1, 2, 0, 1, 2};
    uint32_t B[2][8];
    u64 xr2[2][2];
    ldsm_b(B[0], sb + ((u0 + 0) & 7) * SLOT_SZ, 0, bc);
    #pragma unroll
    for (int st = 0; st < 6; st++) {
        if (st == 0 || st == 3) {
            const int f = f0 + (st == 3 ? 1 : 0);
            #pragma unroll
            for (int mt = 0; mt < 2; mt++) {
                xr2[mt][0] = dup2(xs[(m0 + mt * 16 + r) * 40 + f]);
                xr2[mt][1] = dup2(xs[(m0 + mt * 16 + r + 8) * 40 + f]);
            }
        }
        if (st < 5)
            ldsm_b(B[(st + 1) & 1], sb + ((u0 + so[st + 1]) & 7) * SLOT_SZ,
                   (uint32_t)ko[st + 1], bc);
        const int q = qj[st];
        #pragma unroll
        for (int mt = 0; mt < 2; mt++) {
            uint32_t A[4];
            A[0] = amul(xr2[mt][0], xa2a[mt][q][0]);
            A[1] = amul(xr2[mt][1], xa2a[mt][q][1]);
            if (q < 2) {
                A[2] = amul(xr2[mt][0], xa2b[mt][q][0]);
                A[3] = amul(xr2[mt][1], xa2b[mt][q][1]);
            } else { A[2] = 0u; A[3] = 0u; }
            #pragma unroll
            for (int ht = 0; ht < 4; ht++)
                MMA16816H(acc[mt][ht], A, B[st & 1][ht * 2], B[st & 1][ht * 2 + 1]);
        }
    }
}

// ---------------- L2 group: 4 chunks, 8 ks-blocks, B ping-pong ----------------
__device__ __forceinline__ void l2_group(
    uint32_t sb, int g, const float* xs, const float* h1s,
    u64 hv2[2][2][4], int& f_cur, int& qq_cur,
    float acc[2][4][4], int m0, int r, int c2, const BC& bc)
{
    const int u0 = NL1U + 4 * g;
    uint32_t B[2][8];
    u64 xr2[2][2];
    ldsm_b(B[0], sb + (u0 & 7) * SLOT_SZ, 0, bc);
    #pragma unroll
    for (int st = 0; st < 8; st++) {
        if ((st & 1) == 0) {
            if (f_cur == F0n) { f_cur = 0; qq_cur++; }
            if (f_cur == 0) {
                #pragma unroll
                for (int mt = 0; mt < 2; mt++) {
                    const int n = m0 + mt * 16 + r;
                    #pragma unroll
                    for (int ks = 0; ks < 2; ks++) {
                        const int q0 = qq_cur * 32 + ks * 16 + c2;
                        hv2[mt][ks][0] = *(const u64*)&h1s[n * 132 + q0];
                        hv2[mt][ks][1] = *(const u64*)&h1s[(n + 8) * 132 + q0];
                        hv2[mt][ks][2] = *(const u64*)&h1s[n * 132 + q0 + 8];
                        hv2[mt][ks][3] = *(const u64*)&h1s[(n + 8) * 132 + q0 + 8];
                    }
                }
            }
            #pragma unroll
            for (int mt = 0; mt < 2; mt++) {
                xr2[mt][0] = dup2(xs[(m0 + mt * 16 + r) * 40 + f_cur]);
                xr2[mt][1] = dup2(xs[(m0 + mt * 16 + r + 8) * 40 + f_cur]);
            }
        }
        if (st < 7) {
            const int nst = st + 1;
            ldsm_b(B[nst & 1], sb + ((u0 + (nst >> 1)) & 7) * SLOT_SZ,
                   (uint32_t)((nst & 1) * 32), bc);
        }
        const int ks = st & 1;
        #pragma unroll
        for (int mt = 0; mt < 2; mt++) {
            uint32_t A[4];
            A[0] = amul(xr2[mt][0], hv2[mt][ks][0]);
            A[1] = amul(xr2[mt][1], hv2[mt][ks][1]);
            A[2] = amul(xr2[mt][0], hv2[mt][ks][2]);
            A[3] = amul(xr2[mt][1], hv2[mt][ks][3]);
            #pragma unroll
            for (int ht = 0; ht < 4; ht++)
                MMA16816H(acc[mt][ht], A, B[ks][ht * 2], B[ks][ht * 2 + 1]);
        }
        if (st & 1) f_cur++;
    }
}

// ---------------- main kernel: 256 threads, 2 CTAs/SM ----------------
__global__ __launch_bounds__(256, 2)
void cin_main(const float* __restrict__ x, float* __restrict__ out) {
    extern __shared__ __align__(1024) char smem[];
    const uint32_t sb = smem_u32(smem);
    float* xs  = (float*)(smem + XS_OFF);
    float* h1s = (float*)(smem + H1S_OFF);

    const int tid  = threadIdx.x;
    const int lane = tid & 31;
    const int warp = tid >> 5;            // 0..7
    const int m0 = (warp & 1) * 32;       // 2 m-groups (n = 64)
    const int h0 = (warp >> 1) * 32;      // 4 h-groups
    const int b0 = blockIdx.x * 4;        // 4 batches (64 columns) per CTA
    const int r  = lane >> 2;
    const int c2 = (lane & 3) * 2;

    BC bc;
    #pragma unroll
    for (int pr = 0; pr < 2; pr++) {
        int hB = h0 + pr * 16 + (lane >> 4) * 8 + (lane & 7);
        bc.xo[pr]  = (uint32_t)(hB & 7) << 4;
        bc.row[pr] = (uint32_t)(hB & 63) * 128;
        bc.hf[pr]  = (uint32_t)(hB >> 6) * 64;
    }
    bc.sel = (uint32_t)((lane >> 3) & 1) * 16;

    // prologue: stage units 0-3, 4-7
    stage_unit(sb, 0, tid); stage_unit(sb, 1, tid);
    stage_unit(sb, 2, tid); stage_unit(sb, 3, tid); CP_COMMIT();
    stage_unit(sb, 4, tid); stage_unit(sb, 5, tid);
    stage_unit(sb, 6, tid); stage_unit(sb, 7, tid); CP_COMMIT();

    // xs[n][f], n = (b_local<<4)|d ; col 39 zeroed
    for (int i = tid; i < F0n * 64; i += 256) {
        int f = i >> 6, cc = i & 63;
        int b = b0 + (cc >> 4), d = cc & 15;
        xs[cc * 40 + f] = x[(b * F0n + f) * Dn + d];
    }
    for (int i = tid; i < 64; i += 256) xs[i * 40 + 39] = 0.f;
    CP_WAIT1();
    __syncthreads();

    float acc[2][4][4];
    #pragma unroll
    for (int mt = 0; mt < 2; mt++)
        #pragma unroll
        for (int ht = 0; ht < 4; ht++)
            #pragma unroll
            for (int j = 0; j < 4; j++) acc[mt][ht][j] = 0.f;

    // resident x pairs (packed f32x2)
    u64 xa2a[2][3][2], xa2b[2][2][2];
    #pragma unroll
    for (int mt = 0; mt < 2; mt++) {
        const int n = m0 + mt * 16 + r;
        #pragma unroll
        for (int ks = 0; ks < 3; ks++) {
            const int q0 = ks * 16 + c2;                 // <= 38; q0+1 <= 39 (col 39 = 0)
            xa2a[mt][ks][0] = *(const u64*)&xs[n * 40 + q0];
            xa2a[mt][ks][1] = *(const u64*)&xs[(n + 8) * 40 + q0];
        }
        #pragma unroll
        for (int ks = 0; ks < 2; ks++) {
            const int q0 = ks * 16 + c2 + 8;             // <= 31, always valid
            xa2b[mt][ks][0] = *(const u64*)&xs[n * 40 + q0];
            xa2b[mt][ks][1] = *(const u64*)&xs[(n + 8) * 40 + q0];
        }
    }

    // ================= Layer 1 =================
    #pragma unroll 1
    for (int g = 0; g < NG1; g++) {
        l1_group(sb, g, xs, xa2a, xa2b, acc, m0, r, bc);
        CP_WAIT0();
        __syncthreads();
        const int t = 4 * g + 8;                          // max 87 < NUNIT
        stage_unit(sb, t, tid);     stage_unit(sb, t + 1, tid);
        stage_unit(sb, t + 2, tid); stage_unit(sb, t + 3, tid);
        CP_COMMIT();
    }

    // L1 epilogue: acc -> h1s fp32 (feeds L2 resident + out1)
    #pragma unroll
    for (int mt = 0; mt < 2; mt++)
        #pragma unroll
        for (int ht = 0; ht < 4; ht++) {
            const int n = m0 + mt * 16 + r;
            const int h = h0 + ht * 8 + c2;
            *(float2*)&h1s[n * 132 + h] = make_float2(acc[mt][ht][0], acc[mt][ht][1]);
            *(float2*)&h1s[(n + 8) * 132 + h] = make_float2(acc[mt][ht][2], acc[mt][ht][3]);
        }
    __syncthreads();
    #pragma unroll
    for (int rr = 0; rr < 2; rr++) {
        const int idx = rr * 256 + tid;                  // 512 outputs (4 bl x 128 h)
        const int bl = idx >> 7, h = idx & 127;
        float s = 0.f;
        #pragma unroll
        for (int d = 0; d < 16; d++) s += h1s[(bl * 16 + d) * 132 + h];
        out[(b0 + bl) * HOUT + h] = s;
    }
    __syncthreads();

    // ================= Layer 2 =================
    #pragma unroll
    for (int mt = 0; mt < 2; mt++)
        #pragma unroll
        for (int ht = 0; ht < 4; ht++)
            #pragma unroll
            for (int j = 0; j < 4; j++) acc[mt][ht][j] = 0.f;

    {
        u64 hv2[2][2][4];
        int f_cur = 0, qq_cur = 0;
        #pragma unroll 1
        for (int g = 0; g < NG2; g++) {
            l2_group(sb, g, xs, h1s, hv2, f_cur, qq_cur, acc, m0, r, c2, bc);
            CP_WAIT0();
            __syncthreads();
            const int t = NL1U + 4 * g + 8;
            #pragma unroll
            for (int i = 0; i < 4; i++)
                if (t + i < NUNIT) stage_unit(sb, t + i, tid);
            CP_COMMIT();
        }
    }

    // L2 epilogue
    #pragma unroll
    for (int mt = 0; mt < 2; mt++)
        #pragma unroll
        for (int ht = 0; ht < 4; ht++) {
            const int n = m0 + mt * 16 + r;
            const int h = h0 + ht * 8 + c2;
            *(float2*)&h1s[n * 132 + h] = make_float2(acc[mt][ht][0], acc[mt][ht][1]);
            *(float2*)&h1s[(n + 8) * 132 + h] = make_float2(acc[mt][ht][2], acc[mt][ht][3]);
        }
    __syncthreads();
    #pragma unroll
    for (int rr = 0; rr < 2; rr++) {
        const int idx = rr * 256 + tid;
        const int bl = idx >> 7, h = idx & 127;
        float s = 0.f;
        #pragma unroll
        for (int d = 0; d < 16; d++) s += h1s[(bl * 16 + d) * 132 + h];
        out[(b0 + bl) * HOUT + 128 + h] = s;
    }
}

extern "C" void kernel_launch(void* const* d_in, const int* in_sizes, int n_in,
                              void* d_out, int out_size) {
    const float* xin = (const float*)d_in[0];
    const float* W0  = (const float*)d_in[1];
    const float* W1  = (const float*)d_in[2];
    float* out = (float*)d_out;

    prep_w<<<(NUNIT * 4096 + 255) / 256, 256>>>(W0, W1);

    cudaFuncSetAttribute(cin_main, cudaFuncAttributeMaxDynamicSharedMemorySize, SMEM_TOTAL);
    cin_main<<<512, 256, SMEM_TOTAL>>>(xin, out);
}